// round 4
// baseline (speedup 1.0000x reference)
#include <cuda_runtime.h>
#include <cuda_bf16.h>
#include <math.h>

#define N_GENE  20000
#define N_TRAIN 4096
#define N_EDGES 131072
#define SRC     2500
#define DSTD    2675
#define HD      2500
#define OUTD    2500
#define NC      16
#define TRAINF  (DSTD - NC)   // 2659
#define EPS_F   1e-5f
#define SLOPE_F 0.01f

// ---------------- scratch (device globals; no allocations allowed) ----------
__device__ float g_dst [(size_t)N_TRAIN * DSTD];   // concat(train_feats, y_hat)
__device__ float g_agg [(size_t)N_TRAIN * SRC];    // neighbor mean (shared conv3/conv4)
__device__ float g_deg [N_TRAIN];
__device__ float g_h1  [(size_t)N_TRAIN * HD];
__device__ float g_q   [(size_t)N_TRAIN * HD];
__device__ float g_k   [(size_t)N_TRAIN * HD];
__device__ float g_v   [(size_t)N_TRAIN * HD];
__device__ float g_kT  [(size_t)HD * N_TRAIN];
__device__ float g_S   [(size_t)N_TRAIN * N_TRAIN];
__device__ float g_av  [(size_t)N_TRAIN * HD];
__device__ float g_h2  [(size_t)N_TRAIN * HD];
__device__ float g_h3  [(size_t)N_TRAIN * OUTD];
__device__ float g_t   [(size_t)N_TRAIN * OUTD];
__device__ float g_psum[32 * HD];
__device__ float g_psq [32 * HD];
__device__ float g_bna [HD];
__device__ float g_bnc [HD];

// ---------------- small utility kernels -------------------------------------
__global__ void k_zero(float* p, long n) {
    long i = (long)blockIdx.x * blockDim.x + threadIdx.x;
    if (i < n) p[i] = 0.0f;
}

__global__ void k_concat(const float* __restrict__ tf, const float* __restrict__ yh,
                         float* __restrict__ dst) {
    long i = (long)blockIdx.x * blockDim.x + threadIdx.x;
    long total = (long)N_TRAIN * DSTD;
    if (i >= total) return;
    int r = (int)(i / DSTD), c = (int)(i % DSTD);
    dst[i] = (c < TRAINF) ? tf[(long)r * TRAINF + c] : yh[(long)r * NC + (c - TRAINF)];
}

__global__ void k_deg(const int* __restrict__ di, float* __restrict__ deg) {
    int e = blockIdx.x * blockDim.x + threadIdx.x;
    if (e < N_EDGES) atomicAdd(&deg[di[e]], 1.0f);
}

// one block per edge: agg[dst] += gene[src]
__global__ void k_scatter(const float* __restrict__ gene, const int* __restrict__ si,
                          const int* __restrict__ di, float* __restrict__ agg) {
    int e = blockIdx.x;
    int s = si[e], d = di[e];
    const float* g = gene + (long)s * SRC;
    float* a = agg + (long)d * SRC;
    for (int c = threadIdx.x; c < SRC; c += blockDim.x)
        atomicAdd(&a[c], g[c]);
}

__global__ void k_mean(float* __restrict__ agg, const float* __restrict__ deg) {
    long i = (long)blockIdx.x * blockDim.x + threadIdx.x;
    long total = (long)N_TRAIN * SRC;
    if (i >= total) return;
    int r = (int)(i / SRC);
    agg[i] *= 1.0f / fmaxf(deg[r], 1.0f);
}

// ---------------- SGEMM: C = act( alpha*(A@B) + bias + (acc? C:0) ) ---------
#define BM 128
#define BN 128
#define BK 8

__global__ __launch_bounds__(256, 2)
void k_sgemm(const float* __restrict__ A, const float* __restrict__ B,
             float* __restrict__ C, int M, int N, int K,
             const float* __restrict__ bias, float alpha,
             int accumulate, int relu_act) {
    __shared__ float As[BK][BM];
    __shared__ float Bs[BK][BN];
    int tid = threadIdx.x;
    int tx = tid & 15, ty = tid >> 4;
    int m0 = blockIdx.y * BM, n0 = blockIdx.x * BN;
    float acc[8][8] = {};

    for (int k0 = 0; k0 < K; k0 += BK) {
        #pragma unroll
        for (int i = 0; i < 4; i++) {
            int idx = tid * 4 + i;                 // 0..1023
            int m = idx >> 3, k = idx & 7;
            float va = 0.0f;
            if (m0 + m < M && k0 + k < K) va = A[(long)(m0 + m) * K + k0 + k];
            As[k][m] = va;
        }
        #pragma unroll
        for (int i = 0; i < 4; i++) {
            int idx = tid + i * 256;               // 0..1023
            int k = idx >> 7, n = idx & 127;
            float vb = 0.0f;
            if (k0 + k < K && n0 + n < N) vb = B[(long)(k0 + k) * N + n0 + n];
            Bs[k][n] = vb;
        }
        __syncthreads();
        #pragma unroll
        for (int kk = 0; kk < BK; kk++) {
            float a[8], b[8];
            #pragma unroll
            for (int i = 0; i < 8; i++) a[i] = As[kk][ty * 8 + i];
            #pragma unroll
            for (int j = 0; j < 8; j++) b[j] = Bs[kk][tx * 8 + j];
            #pragma unroll
            for (int i = 0; i < 8; i++)
                #pragma unroll
                for (int j = 0; j < 8; j++)
                    acc[i][j] += a[i] * b[j];
        }
        __syncthreads();
    }

    #pragma unroll
    for (int i = 0; i < 8; i++) {
        int m = m0 + ty * 8 + i;
        if (m >= M) continue;
        #pragma unroll
        for (int j = 0; j < 8; j++) {
            int n = n0 + tx * 8 + j;
            if (n >= N) continue;
            float v = acc[i][j] * alpha;
            if (bias) v += bias[n];
            if (accumulate) v += C[(long)m * N + n];
            if (relu_act) v = fmaxf(v, 0.0f);
            C[(long)m * N + n] = v;
        }
    }
}

// ---------------- transpose (for k -> kT) ------------------------------------
__global__ void k_transpose(const float* __restrict__ in, float* __restrict__ out,
                            int R, int Ccols) {
    __shared__ float t[32][33];
    int c0 = blockIdx.x * 32, r0 = blockIdx.y * 32;
    int x = threadIdx.x, y = threadIdx.y;   // 32 x 8
    for (int i = y; i < 32; i += 8) {
        int r = r0 + i, c = c0 + x;
        t[i][x] = (r < R && c < Ccols) ? in[(long)r * Ccols + c] : 0.0f;
    }
    __syncthreads();
    for (int i = y; i < 32; i += 8) {
        int r = c0 + i, c = r0 + x;          // out is [Ccols x R]
        if (r < Ccols && c < R) out[(long)r * R + c] = t[x][i];
    }
}

// ---------------- row softmax ------------------------------------------------
__global__ void k_softmax(float* __restrict__ S, int n) {
    int r = blockIdx.x;
    float* row = S + (long)r * n;
    __shared__ float red[256];
    int tid = threadIdx.x;

    float mx = -INFINITY;
    for (int i = tid; i < n; i += 256) mx = fmaxf(mx, row[i]);
    red[tid] = mx; __syncthreads();
    for (int s = 128; s > 0; s >>= 1) {
        if (tid < s) red[tid] = fmaxf(red[tid], red[tid + s]);
        __syncthreads();
    }
    mx = red[0]; __syncthreads();

    float sum = 0.0f;
    for (int i = tid; i < n; i += 256) {
        float e = __expf(row[i] - mx);
        row[i] = e;
        sum += e;
    }
    red[tid] = sum; __syncthreads();
    for (int s = 128; s > 0; s >>= 1) {
        if (tid < s) red[tid] += red[tid + s];
        __syncthreads();
    }
    float inv = 1.0f / red[0];
    for (int i = tid; i < n; i += 256) row[i] *= inv;
}

// ---------------- BatchNorm (over rows) --------------------------------------
__global__ void k_bn_partial(const float* __restrict__ X, int N) {
    int col = blockIdx.x * 256 + threadIdx.x;
    int rt = blockIdx.y;
    if (col >= N) return;
    const int RPT = N_TRAIN / 32;  // 128
    float s = 0.0f, q = 0.0f;
    int r0 = rt * RPT;
    for (int r = r0; r < r0 + RPT; r++) {
        float v = X[(long)r * N + col];
        s += v; q += v * v;
    }
    g_psum[rt * N + col] = s;
    g_psq [rt * N + col] = q;
}

__global__ void k_bn_final(const float* __restrict__ g, const float* __restrict__ b, int N) {
    int col = blockIdx.x * 256 + threadIdx.x;
    if (col >= N) return;
    float s = 0.0f, q = 0.0f;
    for (int t = 0; t < 32; t++) { s += g_psum[t * N + col]; q += g_psq[t * N + col]; }
    float m = s / (float)N_TRAIN;
    float var = q / (float)N_TRAIN - m * m;
    float sc = g[col] * rsqrtf(var + EPS_F);
    g_bna[col] = sc;
    g_bnc[col] = b[col] - m * sc;
}

__global__ void k_bn_apply(const float* __restrict__ X, float* __restrict__ Y, int N) {
    long i = (long)blockIdx.x * blockDim.x + threadIdx.x;
    long total = (long)N_TRAIN * N;
    if (i >= total) return;
    int col = (int)(i % N);
    float v = X[i] * g_bna[col] + g_bnc[col];
    Y[i] = (v >= 0.0f) ? v : SLOPE_F * v;
}

// ---------------- LayerNorm + leaky (per row) --------------------------------
__global__ void k_ln_leaky(float* __restrict__ X, const float* __restrict__ g,
                           const float* __restrict__ b, int N) {
    int r = blockIdx.x;
    float* row = X + (long)r * N;
    __shared__ float r1[256], r2[256];
    int tid = threadIdx.x;
    float s = 0.0f, q = 0.0f;
    for (int i = tid; i < N; i += 256) { float v = row[i]; s += v; q += v * v; }
    r1[tid] = s; r2[tid] = q; __syncthreads();
    for (int st = 128; st > 0; st >>= 1) {
        if (tid < st) { r1[tid] += r1[tid + st]; r2[tid] += r2[tid + st]; }
        __syncthreads();
    }
    float m = r1[0] / (float)N;
    float var = r2[0] / (float)N - m * m;
    float inv = rsqrtf(var + EPS_F);
    for (int i = tid; i < N; i += 256) {
        float v = (row[i] - m) * inv * g[i] + b[i];
        row[i] = (v >= 0.0f) ? v : SLOPE_F * v;
    }
}

// ---------------- final tiny GEMM: Y[4096x16] = T @ Wce + bce ----------------
__global__ void k_out_gemm(const float* __restrict__ T, const float* __restrict__ W,
                           const float* __restrict__ bias, float* __restrict__ Y) {
    int r = blockIdx.x;
    int tid = threadIdx.x;
    int col = tid & 15, kg = tid >> 4;     // 16 cols x 16 k-groups
    float acc = 0.0f;
    for (int k = kg; k < OUTD; k += 16)
        acc += T[(long)r * OUTD + k] * W[k * NC + col];
    __shared__ float red[256];
    red[tid] = acc; __syncthreads();
    if (kg == 0) {
        float s = 0.0f;
        for (int t = 0; t < 16; t++) s += red[col + 16 * t];
        Y[(long)r * NC + col] = s + bias[col];
    }
}

// ---------------- launch -----------------------------------------------------
static inline int cdiv(long a, long b) { return (int)((a + b - 1) / b); }

extern "C" void kernel_launch(void* const* d_in, const int* in_sizes, int n_in,
                              void* d_out, int out_size) {
    const float* gene   = (const float*)d_in[0];
    const float* trainf = (const float*)d_in[1];
    const float* yhat   = (const float*)d_in[2];
    const int*   esrc   = (const int*)  d_in[3];
    const int*   edst   = (const int*)  d_in[4];
    const float* Wself3 = (const float*)d_in[5];
    const float* Wneigh3= (const float*)d_in[6];
    const float* b3     = (const float*)d_in[7];
    const float* bn3g   = (const float*)d_in[8];
    const float* bn3b   = (const float*)d_in[9];
    const float* Wq     = (const float*)d_in[10];
    const float* Wk     = (const float*)d_in[11];
    const float* Wv     = (const float*)d_in[12];
    const float* bq     = (const float*)d_in[13];
    const float* bk     = (const float*)d_in[14];
    const float* bv     = (const float*)d_in[15];
    const float* Wo     = (const float*)d_in[16];
    const float* bo     = (const float*)d_in[17];
    const float* ln2g   = (const float*)d_in[18];
    const float* ln2b   = (const float*)d_in[19];
    const float* Wself4 = (const float*)d_in[20];
    const float* Wneigh4= (const float*)d_in[21];
    const float* b4     = (const float*)d_in[22];
    const float* bn4g   = (const float*)d_in[23];
    const float* bn4b   = (const float*)d_in[24];
    const float* Wlin2  = (const float*)d_in[25];
    const float* blin2  = (const float*)d_in[26];
    const float* Wce    = (const float*)d_in[27];
    const float* bce    = (const float*)d_in[28];

    float* out_xhat = (float*)d_out;                       // [4096 x 2500]
    float* out_y    = out_xhat + (size_t)N_TRAIN * OUTD;   // [4096 x 16]

    float *p_dst, *p_agg, *p_deg, *p_h1, *p_q, *p_k, *p_v, *p_kT, *p_S,
          *p_av, *p_h2, *p_h3, *p_t;
    cudaGetSymbolAddress((void**)&p_dst, g_dst);
    cudaGetSymbolAddress((void**)&p_agg, g_agg);
    cudaGetSymbolAddress((void**)&p_deg, g_deg);
    cudaGetSymbolAddress((void**)&p_h1,  g_h1);
    cudaGetSymbolAddress((void**)&p_q,   g_q);
    cudaGetSymbolAddress((void**)&p_k,   g_k);
    cudaGetSymbolAddress((void**)&p_v,   g_v);
    cudaGetSymbolAddress((void**)&p_kT,  g_kT);
    cudaGetSymbolAddress((void**)&p_S,   g_S);
    cudaGetSymbolAddress((void**)&p_av,  g_av);
    cudaGetSymbolAddress((void**)&p_h2,  g_h2);
    cudaGetSymbolAddress((void**)&p_h3,  g_h3);
    cudaGetSymbolAddress((void**)&p_t,   g_t);

    const long n_dst  = (long)N_TRAIN * DSTD;
    const long n_hd   = (long)N_TRAIN * HD;

    // 1) concat dst features
    k_concat<<<cdiv(n_dst, 256), 256>>>(trainf, yhat, p_dst);

    // 2) neighbor mean aggregation (shared by conv3 & conv4)
    k_zero<<<cdiv(n_hd, 256), 256>>>(p_agg, n_hd);
    k_zero<<<cdiv(N_TRAIN, 256), 256>>>(p_deg, N_TRAIN);
    k_deg<<<cdiv(N_EDGES, 256), 256>>>(edst, p_deg);
    k_scatter<<<N_EDGES, 256>>>(gene, esrc, edst, p_agg);
    k_mean<<<cdiv(n_hd, 256), 256>>>(p_agg, p_deg);

    dim3 gHD(cdiv(HD, BN), cdiv(N_TRAIN, BM));       // N=2500 GEMMs
    dim3 gS (cdiv(N_TRAIN, BN), cdiv(N_TRAIN, BM));  // N=4096 GEMM

    // 3) conv3: h1 = dst@Wself3 + b3 + mean@Wneigh3
    k_sgemm<<<gHD, 256>>>(p_dst, Wself3, p_h1, N_TRAIN, HD, DSTD, b3, 1.0f, 0, 0);
    k_sgemm<<<gHD, 256>>>(p_agg, Wneigh3, p_h1, N_TRAIN, HD, SRC, nullptr, 1.0f, 1, 0);

    // 4) BN3 + leaky
    k_bn_partial<<<dim3(cdiv(HD, 256), 32), 256>>>(p_h1, HD);
    k_bn_final<<<cdiv(HD, 256), 256>>>(bn3g, bn3b, HD);
    k_bn_apply<<<cdiv(n_hd, 256), 256>>>(p_h1, p_h1, HD);

    // 5) attention
    k_sgemm<<<gHD, 256>>>(p_h1, Wq, p_q, N_TRAIN, HD, HD, bq, 1.0f, 0, 0);
    k_sgemm<<<gHD, 256>>>(p_h1, Wk, p_k, N_TRAIN, HD, HD, bk, 1.0f, 0, 0);
    k_sgemm<<<gHD, 256>>>(p_h1, Wv, p_v, N_TRAIN, HD, HD, bv, 1.0f, 0, 0);
    k_transpose<<<dim3(cdiv(HD, 32), cdiv(N_TRAIN, 32)), dim3(32, 8)>>>(p_k, p_kT, N_TRAIN, HD);
    k_sgemm<<<gS, 256>>>(p_q, p_kT, p_S, N_TRAIN, N_TRAIN, HD, nullptr, 0.02f, 0, 0); // 1/sqrt(2500)
    k_softmax<<<N_TRAIN, 256>>>(p_S, N_TRAIN);
    k_sgemm<<<gHD, 256>>>(p_S, p_v, p_av, N_TRAIN, HD, N_TRAIN, nullptr, 1.0f, 0, 0);
    k_sgemm<<<gHD, 256>>>(p_av, Wo, p_h2, N_TRAIN, HD, HD, bo, 1.0f, 0, 0);

    // 6) LN + leaky
    k_ln_leaky<<<N_TRAIN, 256>>>(p_h2, ln2g, ln2b, HD);

    // 7) conv4
    k_sgemm<<<gHD, 256>>>(p_h2, Wself4, p_h3, N_TRAIN, OUTD, HD, b4, 1.0f, 0, 0);
    k_sgemm<<<gHD, 256>>>(p_agg, Wneigh4, p_h3, N_TRAIN, OUTD, SRC, nullptr, 1.0f, 1, 0);

    // 8) BN4 + leaky -> x_hat (directly into output)
    k_bn_partial<<<dim3(cdiv(OUTD, 256), 32), 256>>>(p_h3, OUTD);
    k_bn_final<<<cdiv(OUTD, 256), 256>>>(bn4g, bn4b, OUTD);
    k_bn_apply<<<cdiv(n_hd, 256), 256>>>(p_h3, out_xhat, OUTD);

    // 9) head: y = relu(x_hat@Wlin2 + blin2) @ Wce + bce
    k_sgemm<<<gHD, 256>>>(out_xhat, Wlin2, p_t, N_TRAIN, OUTD, OUTD, blin2, 1.0f, 0, 1);
    k_out_gemm<<<N_TRAIN, 256>>>(p_t, Wce, bce, out_y);
}

// round 8
// speedup vs baseline: 2.7059x; 2.7059x over previous
#include <cuda_runtime.h>
#include <cuda_bf16.h>
#include <math.h>
#include <stdint.h>

#define N_GENE  20000
#define N_TRAIN 4096
#define N_EDGES 131072
#define SRC     2500
#define DSTD    2675
#define HD      2500
#define OUTD    2500
#define NC      16
#define TRAINF  (DSTD - NC)   // 2659
#define EPS_F   1e-5f
#define SLOPE_F 0.01f

// padded K dims (multiple of 32 BEFORE the 3-slot interleave)
#define KP_DST  2688
#define KP_HD   2560
#define KP_S    4096
#define NP_HD   2560   // 20 col tiles
#define NP_S    4096   // 32 col tiles

// ---------------- fp32 scratch ----------------------------------------------
__device__ float g_dst [(size_t)N_TRAIN * DSTD];
__device__ float g_agg [(size_t)N_TRAIN * SRC];
__device__ float g_deg [N_TRAIN];
__device__ float g_h1  [(size_t)N_TRAIN * HD];
__device__ float g_q   [(size_t)N_TRAIN * HD];
__device__ float g_k   [(size_t)N_TRAIN * HD];
__device__ float g_v   [(size_t)N_TRAIN * HD];
__device__ float g_S   [(size_t)N_TRAIN * N_TRAIN];
__device__ float g_av  [(size_t)N_TRAIN * HD];
__device__ float g_h2  [(size_t)N_TRAIN * HD];
__device__ float g_h3  [(size_t)N_TRAIN * OUTD];
__device__ float g_t   [(size_t)N_TRAIN * OUTD];
__device__ float g_psum[32 * HD];
__device__ float g_psq [32 * HD];
__device__ float g_bna [HD];
__device__ float g_bnc [HD];

// ---------------- bf16 3-slot interleaved buffers ----------------------------
// A pattern per k: [ah, al, ah] ; B pattern per k: [bh, bh, bl]
// dot(A',B') = ah*bh + al*bh + ah*bl = (ah+al)(bh+bl) - al*bl  (residual ~2^-16)
__device__ __nv_bfloat16 g_A0[(size_t)4096 * 3 * 4096];
__device__ __nv_bfloat16 g_A1[(size_t)4096 * 3 * KP_HD];
__device__ __nv_bfloat16 g_B0[(size_t)4096 * 3 * KP_HD];

// =============================================================================
// PTX helpers (portable compute_80-level only)
// =============================================================================
__device__ __forceinline__ uint32_t smem_to_u32(const void* p) {
    uint32_t a;
    asm("{ .reg .u64 t; cvta.to.shared.u64 t, %1; cvt.u32.u64 %0, t; }" : "=r"(a) : "l"(p));
    return a;
}
__device__ __forceinline__ void cp16(uint32_t s, const void* g) {
    asm volatile("cp.async.cg.shared.global [%0], [%1], 16;" :: "r"(s), "l"(g));
}
__device__ __forceinline__ void cp_commit() { asm volatile("cp.async.commit_group;" ::: "memory"); }
__device__ __forceinline__ void cp_wait2()  { asm volatile("cp.async.wait_group 2;" ::: "memory"); }

__device__ __forceinline__ void ldsm4(uint32_t* r, uint32_t addr) {
    asm volatile("ldmatrix.sync.aligned.m8n8.x4.shared.b16 {%0,%1,%2,%3}, [%4];"
                 : "=r"(r[0]), "=r"(r[1]), "=r"(r[2]), "=r"(r[3]) : "r"(addr));
}
__device__ __forceinline__ void mma_bf16(float* c, const uint32_t* a, uint32_t b0, uint32_t b1) {
    asm volatile(
        "mma.sync.aligned.m16n8k16.row.col.f32.bf16.bf16.f32 "
        "{%0,%1,%2,%3}, {%4,%5,%6,%7}, {%8,%9}, {%0,%1,%2,%3};\n"
        : "+f"(c[0]), "+f"(c[1]), "+f"(c[2]), "+f"(c[3])
        : "r"(a[0]), "r"(a[1]), "r"(a[2]), "r"(a[3]), "r"(b0), "r"(b1));
}
__device__ __forceinline__ uint32_t pack2(__nv_bfloat16 lo, __nv_bfloat16 hi) {
    uint16_t a = __bfloat16_as_ushort(lo), b = __bfloat16_as_ushort(hi);
    return (uint32_t)a | ((uint32_t)b << 16);
}

// =============================================================================
// small utility kernels
// =============================================================================
__global__ void k_zero(float* p, long n) {
    long i = (long)blockIdx.x * blockDim.x + threadIdx.x;
    if (i < n) p[i] = 0.0f;
}

__global__ void k_concat(const float* __restrict__ tf, const float* __restrict__ yh,
                         float* __restrict__ dst) {
    long i = (long)blockIdx.x * blockDim.x + threadIdx.x;
    long total = (long)N_TRAIN * DSTD;
    if (i >= total) return;
    int r = (int)(i / DSTD), c = (int)(i % DSTD);
    dst[i] = (c < TRAINF) ? tf[(long)r * TRAINF + c] : yh[(long)r * NC + (c - TRAINF)];
}

__global__ void k_deg(const int* __restrict__ di, float* __restrict__ deg) {
    int e = blockIdx.x * blockDim.x + threadIdx.x;
    if (e < N_EDGES) atomicAdd(&deg[di[e]], 1.0f);
}

__global__ void k_scatter(const float* __restrict__ gene, const int* __restrict__ si,
                          const int* __restrict__ di, float* __restrict__ agg) {
    int e = blockIdx.x;
    int s = si[e], d = di[e];
    const float* g = gene + (long)s * SRC;
    float* a = agg + (long)d * SRC;
    for (int c = threadIdx.x; c < SRC; c += blockDim.x)
        atomicAdd(&a[c], g[c]);
}

__global__ void k_mean(float* __restrict__ agg, const float* __restrict__ deg) {
    long i = (long)blockIdx.x * blockDim.x + threadIdx.x;
    long total = (long)N_TRAIN * SRC;
    if (i >= total) return;
    int r = (int)(i / SRC);
    agg[i] *= 1.0f / fmaxf(deg[r], 1.0f);
}

// fp32 [M x K] -> bf16 [M x 3*Kp], per-k pattern [ah, al, ah]
__global__ void k_split_a3(const float* __restrict__ in, __nv_bfloat16* __restrict__ out,
                           int M, int K, int Kp) {
    long i = (long)blockIdx.x * blockDim.x + threadIdx.x;
    long total = (long)M * (Kp >> 1);
    if (i >= total) return;
    int half = Kp >> 1;
    int r = (int)(i / half), p = (int)(i % half);
    int c0 = 2 * p;
    float v0 = (c0     < K) ? in[(long)r * K + c0]     : 0.0f;
    float v1 = (c0 + 1 < K) ? in[(long)r * K + c0 + 1] : 0.0f;
    __nv_bfloat16 h0 = __float2bfloat16(v0);
    __nv_bfloat16 l0 = __float2bfloat16(v0 - __bfloat162float(h0));
    __nv_bfloat16 h1 = __float2bfloat16(v1);
    __nv_bfloat16 l1 = __float2bfloat16(v1 - __bfloat162float(h1));
    uint32_t* o = (uint32_t*)(out + (long)r * 3 * Kp + 3 * c0);
    o[0] = pack2(h0, l0);   // [h0, l0,
    o[1] = pack2(h0, h1);   //  h0, h1,
    o[2] = pack2(l1, h1);   //  l1, h1]
}

// fp32 [M x K] row-major -> bf16 [M x 3*Kp], per-k pattern [bh, bh, bl]
// (for operands already in B^T orientation, e.g. attention k)
__global__ void k_split_b3_rows(const float* __restrict__ in, __nv_bfloat16* __restrict__ out,
                                int M, int K, int Kp) {
    long i = (long)blockIdx.x * blockDim.x + threadIdx.x;
    long total = (long)M * (Kp >> 1);
    if (i >= total) return;
    int half = Kp >> 1;
    int r = (int)(i / half), p = (int)(i % half);
    int c0 = 2 * p;
    float v0 = (c0     < K) ? in[(long)r * K + c0]     : 0.0f;
    float v1 = (c0 + 1 < K) ? in[(long)r * K + c0 + 1] : 0.0f;
    __nv_bfloat16 h0 = __float2bfloat16(v0);
    __nv_bfloat16 l0 = __float2bfloat16(v0 - __bfloat162float(h0));
    __nv_bfloat16 h1 = __float2bfloat16(v1);
    __nv_bfloat16 l1 = __float2bfloat16(v1 - __bfloat162float(h1));
    uint32_t* o = (uint32_t*)(out + (long)r * 3 * Kp + 3 * c0);
    o[0] = pack2(h0, h0);   // [h0, h0,
    o[1] = pack2(l0, h1);   //  l0, h1,
    o[2] = pack2(h1, l1);   //  h1, l1]
}

// fp32 [K x N] -> transposed bf16 [Np x 3*Kp], per-k pattern [bh, bh, bl]
__global__ void k_split_bt3(const float* __restrict__ in, __nv_bfloat16* __restrict__ out,
                            int K, int N, int Kp, int Np) {
    __shared__ float t[32][33];
    int k0 = blockIdx.x * 32, n0 = blockIdx.y * 32;
    int x = threadIdx.x, y = threadIdx.y;   // 32 x 8
    for (int i = y; i < 32; i += 8) {
        int k = k0 + i, n = n0 + x;
        t[i][x] = (k < K && n < N) ? in[(long)k * N + n] : 0.0f;
    }
    __syncthreads();
    long K2 = 3L * Kp;
    for (int i = y; i < 32; i += 8) {
        int n = n0 + i, k = k0 + x;
        float v = t[x][i];
        __nv_bfloat16 h = __float2bfloat16(v);
        __nv_bfloat16 l = __float2bfloat16(v - __bfloat162float(h));
        __nv_bfloat16* o = out + (long)n * K2 + 3 * k;
        o[0] = h; o[1] = h; o[2] = l;
    }
}

// =============================================================================
// bf16 mma.sync GEMM: C[M x N] = act( alpha*(A@B^T) + bias + (acc?C:0) )
// tile 128x128, BK=32, 4-stage cp.async, 8 warps (4m x 2n), smem stride 80B
// =============================================================================
#define STAGES 4
#define STAGE_BYTES 20480
#define GEMM_SMEM (STAGES * STAGE_BYTES)

__device__ __forceinline__ void g_load_stage(uint32_t sbase, int stage,
    const __nv_bfloat16* A, const __nv_bfloat16* B, int m0, int n0, long K2, int kb)
{
    uint32_t sA = sbase + stage * STAGE_BYTES;
    uint32_t sB = sA + 10240;
    int tid = threadIdx.x;
    #pragma unroll
    for (int i = 0; i < 2; i++) {
        int idx = tid + i * 256;
        int r = idx >> 2, c = idx & 3;
        long gofs = (long)r * K2 + (long)kb * 32 + c * 8;
        cp16(sA + r * 80 + c * 16, (const char*)(A + (long)m0 * K2) + gofs * 2);
        cp16(sB + r * 80 + c * 16, (const char*)(B + (long)n0 * K2) + gofs * 2);
    }
}

__global__ __launch_bounds__(256, 1)
void k_mma_gemm(const __nv_bfloat16* __restrict__ A, const __nv_bfloat16* __restrict__ B,
                float* __restrict__ C, int N, long K2,
                const float* __restrict__ bias, float alpha, int acc, int act) {
    extern __shared__ char smem[];
    uint32_t sbase = smem_to_u32(smem);
    int tid = threadIdx.x;
    int warp = tid >> 5, lane = tid & 31;
    int wm = warp & 3, wn = warp >> 2;
    int m0 = blockIdx.y * 128, n0 = blockIdx.x * 128;

    float accf[2][8][4];
    #pragma unroll
    for (int i = 0; i < 2; i++)
        #pragma unroll
        for (int j = 0; j < 8; j++)
            #pragma unroll
            for (int l = 0; l < 4; l++) accf[i][j][l] = 0.0f;

    const int nkb = (int)(K2 >> 5);

    #pragma unroll
    for (int s = 0; s < STAGES - 1; s++) {
        if (s < nkb) g_load_stage(sbase, s, A, B, m0, n0, K2, s);
        cp_commit();
    }

    int lrow = lane & 15;
    int lcol = (lane >> 4) * 16;

    for (int kb = 0; kb < nkb; kb++) {
        cp_wait2();
        __syncthreads();
        int stage = kb & (STAGES - 1);
        uint32_t sA = sbase + stage * STAGE_BYTES;
        uint32_t sB = sA + 10240;

        #pragma unroll
        for (int kk = 0; kk < 2; kk++) {
            uint32_t a[2][4], bq[4][4];
            #pragma unroll
            for (int mi = 0; mi < 2; mi++)
                ldsm4(a[mi], sA + (wm * 32 + mi * 16 + lrow) * 80 + kk * 32 + lcol);
            #pragma unroll
            for (int nb = 0; nb < 4; nb++)
                ldsm4(bq[nb], sB + (wn * 64 + nb * 16 + lrow) * 80 + kk * 32 + lcol);
            #pragma unroll
            for (int mi = 0; mi < 2; mi++)
                #pragma unroll
                for (int nb = 0; nb < 4; nb++) {
                    mma_bf16(accf[mi][2 * nb],     a[mi], bq[nb][0], bq[nb][2]);
                    mma_bf16(accf[mi][2 * nb + 1], a[mi], bq[nb][1], bq[nb][3]);
                }
        }

        int nk = kb + STAGES - 1;
        if (nk < nkb) g_load_stage(sbase, nk & (STAGES - 1), A, B, m0, n0, K2, nk);
        cp_commit();
    }

    #pragma unroll
    for (int mi = 0; mi < 2; mi++) {
        int row0 = m0 + wm * 32 + mi * 16 + (lane >> 2);
        #pragma unroll
        for (int ni = 0; ni < 8; ni++) {
            int col = n0 + wn * 64 + ni * 8 + (lane & 3) * 2;
            if (col >= N) continue;
            float b0 = 0.f, b1 = 0.f;
            if (bias) { b0 = bias[col]; b1 = bias[col + 1]; }
            #pragma unroll
            for (int h = 0; h < 2; h++) {
                int row = row0 + h * 8;
                float v0 = accf[mi][ni][2 * h]     * alpha + b0;
                float v1 = accf[mi][ni][2 * h + 1] * alpha + b1;
                float* cp = &C[(long)row * N + col];
                if (acc) { float2 p = *(float2*)cp; v0 += p.x; v1 += p.y; }
                if (act) { v0 = fmaxf(v0, 0.f); v1 = fmaxf(v1, 0.f); }
                float2 o; o.x = v0; o.y = v1;
                *(float2*)cp = o;
            }
        }
    }
}

// =============================================================================
// softmax / BN / LN / head
// =============================================================================
__global__ void k_softmax(float* __restrict__ S, int n) {
    int r = blockIdx.x;
    float* row = S + (long)r * n;
    __shared__ float red[256];
    int tid = threadIdx.x;
    float mx = -INFINITY;
    for (int i = tid; i < n; i += 256) mx = fmaxf(mx, row[i]);
    red[tid] = mx; __syncthreads();
    for (int s = 128; s > 0; s >>= 1) {
        if (tid < s) red[tid] = fmaxf(red[tid], red[tid + s]);
        __syncthreads();
    }
    mx = red[0]; __syncthreads();
    float sum = 0.0f;
    for (int i = tid; i < n; i += 256) {
        float e = __expf(row[i] - mx);
        row[i] = e; sum += e;
    }
    red[tid] = sum; __syncthreads();
    for (int s = 128; s > 0; s >>= 1) {
        if (tid < s) red[tid] += red[tid + s];
        __syncthreads();
    }
    float inv = 1.0f / red[0];
    for (int i = tid; i < n; i += 256) row[i] *= inv;
}

__global__ void k_bn_partial(const float* __restrict__ X, int N) {
    int col = blockIdx.x * 256 + threadIdx.x;
    int rt = blockIdx.y;
    if (col >= N) return;
    const int RPT = N_TRAIN / 32;
    float s = 0.0f, q = 0.0f;
    int r0 = rt * RPT;
    for (int r = r0; r < r0 + RPT; r++) {
        float v = X[(long)r * N + col];
        s += v; q += v * v;
    }
    g_psum[rt * N + col] = s;
    g_psq [rt * N + col] = q;
}

__global__ void k_bn_final(const float* __restrict__ g, const float* __restrict__ b, int N) {
    int col = blockIdx.x * 256 + threadIdx.x;
    if (col >= N) return;
    float s = 0.0f, q = 0.0f;
    for (int t = 0; t < 32; t++) { s += g_psum[t * N + col]; q += g_psq[t * N + col]; }
    float m = s / (float)N_TRAIN;
    float var = q / (float)N_TRAIN - m * m;
    float sc = g[col] * rsqrtf(var + EPS_F);
    g_bna[col] = sc;
    g_bnc[col] = b[col] - m * sc;
}

__global__ void k_bn_apply(const float* __restrict__ X, float* __restrict__ Y, int N) {
    long i = (long)blockIdx.x * blockDim.x + threadIdx.x;
    long total = (long)N_TRAIN * N;
    if (i >= total) return;
    int col = (int)(i % N);
    float v = X[i] * g_bna[col] + g_bnc[col];
    Y[i] = (v >= 0.0f) ? v : SLOPE_F * v;
}

__global__ void k_ln_leaky(float* __restrict__ X, const float* __restrict__ g,
                           const float* __restrict__ b, int N) {
    int r = blockIdx.x;
    float* row = X + (long)r * N;
    __shared__ float r1[256], r2[256];
    int tid = threadIdx.x;
    float s = 0.0f, q = 0.0f;
    for (int i = tid; i < N; i += 256) { float v = row[i]; s += v; q += v * v; }
    r1[tid] = s; r2[tid] = q; __syncthreads();
    for (int st = 128; st > 0; st >>= 1) {
        if (tid < st) { r1[tid] += r1[tid + st]; r2[tid] += r2[tid + st]; }
        __syncthreads();
    }
    float m = r1[0] / (float)N;
    float var = r2[0] / (float)N - m * m;
    float inv = rsqrtf(var + EPS_F);
    for (int i = tid; i < N; i += 256) {
        float v = (row[i] - m) * inv * g[i] + b[i];
        row[i] = (v >= 0.0f) ? v : SLOPE_F * v;
    }
}

__global__ void k_out_gemm(const float* __restrict__ T, const float* __restrict__ W,
                           const float* __restrict__ bias, float* __restrict__ Y) {
    int r = blockIdx.x;
    int tid = threadIdx.x;
    int col = tid & 15, kg = tid >> 4;
    float acc = 0.0f;
    for (int k = kg; k < OUTD; k += 16)
        acc += T[(long)r * OUTD + k] * W[k * NC + col];
    __shared__ float red[256];
    red[tid] = acc; __syncthreads();
    if (kg == 0) {
        float s = 0.0f;
        for (int t = 0; t < 16; t++) s += red[col + 16 * t];
        Y[(long)r * NC + col] = s + bias[col];
    }
}

// =============================================================================
// launch
// =============================================================================
static inline int cdiv(long a, long b) { return (int)((a + b - 1) / b); }

extern "C" void kernel_launch(void* const* d_in, const int* in_sizes, int n_in,
                              void* d_out, int out_size) {
    const float* gene   = (const float*)d_in[0];
    const float* trainf = (const float*)d_in[1];
    const float* yhat   = (const float*)d_in[2];
    const int*   esrc   = (const int*)  d_in[3];
    const int*   edst   = (const int*)  d_in[4];
    const float* Wself3 = (const float*)d_in[5];
    const float* Wneigh3= (const float*)d_in[6];
    const float* b3     = (const float*)d_in[7];
    const float* bn3g   = (const float*)d_in[8];
    const float* bn3b   = (const float*)d_in[9];
    const float* Wq     = (const float*)d_in[10];
    const float* Wk     = (const float*)d_in[11];
    const float* Wv     = (const float*)d_in[12];
    const float* bq     = (const float*)d_in[13];
    const float* bk     = (const float*)d_in[14];
    const float* bv     = (const float*)d_in[15];
    const float* Wo     = (const float*)d_in[16];
    const float* bo     = (const float*)d_in[17];
    const float* ln2g   = (const float*)d_in[18];
    const float* ln2b   = (const float*)d_in[19];
    const float* Wself4 = (const float*)d_in[20];
    const float* Wneigh4= (const float*)d_in[21];
    const float* b4     = (const float*)d_in[22];
    const float* bn4g   = (const float*)d_in[23];
    const float* bn4b   = (const float*)d_in[24];
    const float* Wlin2  = (const float*)d_in[25];
    const float* blin2  = (const float*)d_in[26];
    const float* Wce    = (const float*)d_in[27];
    const float* bce    = (const float*)d_in[28];

    float* out_xhat = (float*)d_out;
    float* out_y    = out_xhat + (size_t)N_TRAIN * OUTD;

    float *p_dst, *p_agg, *p_deg, *p_h1, *p_q, *p_k, *p_v, *p_S, *p_av, *p_h2, *p_h3, *p_t;
    __nv_bfloat16 *A0, *A1, *B0;
    cudaGetSymbolAddress((void**)&p_dst, g_dst);
    cudaGetSymbolAddress((void**)&p_agg, g_agg);
    cudaGetSymbolAddress((void**)&p_deg, g_deg);
    cudaGetSymbolAddress((void**)&p_h1,  g_h1);
    cudaGetSymbolAddress((void**)&p_q,   g_q);
    cudaGetSymbolAddress((void**)&p_k,   g_k);
    cudaGetSymbolAddress((void**)&p_v,   g_v);
    cudaGetSymbolAddress((void**)&p_S,   g_S);
    cudaGetSymbolAddress((void**)&p_av,  g_av);
    cudaGetSymbolAddress((void**)&p_h2,  g_h2);
    cudaGetSymbolAddress((void**)&p_h3,  g_h3);
    cudaGetSymbolAddress((void**)&p_t,   g_t);
    cudaGetSymbolAddress((void**)&A0,    g_A0);
    cudaGetSymbolAddress((void**)&A1,    g_A1);
    cudaGetSymbolAddress((void**)&B0,    g_B0);

    cudaFuncSetAttribute(k_mma_gemm, cudaFuncAttributeMaxDynamicSharedMemorySize, GEMM_SMEM);

    const long n_dst = (long)N_TRAIN * DSTD;
    const long n_hd  = (long)N_TRAIN * HD;

    dim3 gHD(NP_HD / 128, 32);
    dim3 gS (NP_S  / 128, 32);
    dim3 tb(32, 8);

    const long spDST = (long)4096 * (KP_DST / 2);
    const long spHD  = (long)4096 * (KP_HD  / 2);
    const long spS   = (long)4096 * (KP_S   / 2);

    // 1) concat
    k_concat<<<cdiv(n_dst, 256), 256>>>(trainf, yhat, p_dst);

    // 2) neighbor mean (shared by conv3 & conv4)
    k_zero<<<cdiv(n_hd, 256), 256>>>(p_agg, n_hd);
    k_zero<<<cdiv(N_TRAIN, 256), 256>>>(p_deg, N_TRAIN);
    k_deg<<<cdiv(N_EDGES, 256), 256>>>(edst, p_deg);
    k_scatter<<<N_EDGES, 256>>>(gene, esrc, edst, p_agg);
    k_mean<<<cdiv(n_hd, 256), 256>>>(p_agg, p_deg);

    // 3) conv3 self: h1 = dst @ Wself3 + b3
    k_split_a3<<<cdiv(spDST, 256), 256>>>(p_dst, A0, 4096, DSTD, KP_DST);
    k_split_bt3<<<dim3(KP_DST / 32, NP_HD / 32), tb>>>(Wself3, B0, DSTD, HD, KP_DST, NP_HD);
    k_mma_gemm<<<gHD, 256, GEMM_SMEM>>>(A0, B0, p_h1, HD, 3L * KP_DST, b3, 1.0f, 0, 0);

    // conv3 neigh: h1 += agg @ Wneigh3  (A1 kept for conv4)
    k_split_a3<<<cdiv(spHD, 256), 256>>>(p_agg, A1, 4096, SRC, KP_HD);
    k_split_bt3<<<dim3(KP_HD / 32, NP_HD / 32), tb>>>(Wneigh3, B0, SRC, HD, KP_HD, NP_HD);
    k_mma_gemm<<<gHD, 256, GEMM_SMEM>>>(A1, B0, p_h1, HD, 3L * KP_HD, nullptr, 1.0f, 1, 0);

    // 4) BN3 + leaky
    k_bn_partial<<<dim3(cdiv(HD, 256), 32), 256>>>(p_h1, HD);
    k_bn_final<<<cdiv(HD, 256), 256>>>(bn3g, bn3b, HD);
    k_bn_apply<<<cdiv(n_hd, 256), 256>>>(p_h1, p_h1, HD);

    // 5) Q, K, V (share h1 split in A0)
    k_split_a3<<<cdiv(spHD, 256), 256>>>(p_h1, A0, 4096, HD, KP_HD);
    k_split_bt3<<<dim3(KP_HD / 32, NP_HD / 32), tb>>>(Wq, B0, HD, HD, KP_HD, NP_HD);
    k_mma_gemm<<<gHD, 256, GEMM_SMEM>>>(A0, B0, p_q, HD, 3L * KP_HD, bq, 1.0f, 0, 0);
    k_split_bt3<<<dim3(KP_HD / 32, NP_HD / 32), tb>>>(Wk, B0, HD, HD, KP_HD, NP_HD);
    k_mma_gemm<<<gHD, 256, GEMM_SMEM>>>(A0, B0, p_k, HD, 3L * KP_HD, bk, 1.0f, 0, 0);
    k_split_bt3<<<dim3(KP_HD / 32, NP_HD / 32), tb>>>(Wv, B0, HD, HD, KP_HD, NP_HD);
    k_mma_gemm<<<gHD, 256, GEMM_SMEM>>>(A0, B0, p_v, HD, 3L * KP_HD, bv, 1.0f, 0, 0);

    // 6) S = softmax(q @ k^T * 0.02)
    //    q: A-pattern split; k (already [4096 x HD] = B^T orientation): row-wise B-pattern
    k_split_a3<<<cdiv(spHD, 256), 256>>>(p_q, A0, 4096, HD, KP_HD);
    k_split_b3_rows<<<cdiv(spHD, 256), 256>>>(p_k, B0, 4096, HD, KP_HD);
    k_mma_gemm<<<gS, 256, GEMM_SMEM>>>(A0, B0, p_S, N_TRAIN, 3L * KP_HD, nullptr, 0.02f, 0, 0);
    k_softmax<<<N_TRAIN, 256>>>(p_S, N_TRAIN);

    // 7) AV = S @ V ; h2 = AV @ Wo + bo
    k_split_a3<<<cdiv(spS, 256), 256>>>(p_S, A0, 4096, N_TRAIN, KP_S);
    k_split_bt3<<<dim3(KP_S / 32, NP_HD / 32), tb>>>(p_v, B0, N_TRAIN, HD, KP_S, NP_HD);
    k_mma_gemm<<<gHD, 256, GEMM_SMEM>>>(A0, B0, p_av, HD, 3L * KP_S, nullptr, 1.0f, 0, 0);

    k_split_a3<<<cdiv(spHD, 256), 256>>>(p_av, A0, 4096, HD, KP_HD);
    k_split_bt3<<<dim3(KP_HD / 32, NP_HD / 32), tb>>>(Wo, B0, HD, HD, KP_HD, NP_HD);
    k_mma_gemm<<<gHD, 256, GEMM_SMEM>>>(A0, B0, p_h2, HD, 3L * KP_HD, bo, 1.0f, 0, 0);

    // 8) LN + leaky
    k_ln_leaky<<<N_TRAIN, 256>>>(p_h2, ln2g, ln2b, HD);

    // 9) conv4: h3 = h2 @ Wself4 + b4 + agg @ Wneigh4
    k_split_a3<<<cdiv(spHD, 256), 256>>>(p_h2, A0, 4096, HD, KP_HD);
    k_split_bt3<<<dim3(KP_HD / 32, NP_HD / 32), tb>>>(Wself4, B0, HD, OUTD, KP_HD, NP_HD);
    k_mma_gemm<<<gHD, 256, GEMM_SMEM>>>(A0, B0, p_h3, OUTD, 3L * KP_HD, b4, 1.0f, 0, 0);
    k_split_bt3<<<dim3(KP_HD / 32, NP_HD / 32), tb>>>(Wneigh4, B0, SRC, OUTD, KP_HD, NP_HD);
    k_mma_gemm<<<gHD, 256, GEMM_SMEM>>>(A1, B0, p_h3, OUTD, 3L * KP_HD, nullptr, 1.0f, 1, 0);

    // 10) BN4 + leaky -> x_hat
    k_bn_partial<<<dim3(cdiv(OUTD, 256), 32), 256>>>(p_h3, OUTD);
    k_bn_final<<<cdiv(OUTD, 256), 256>>>(bn4g, bn4b, OUTD);
    k_bn_apply<<<cdiv(n_hd, 256), 256>>>(p_h3, out_xhat, OUTD);

    // 11) head: t = relu(x_hat @ Wlin2 + blin2) ; y = t @ Wce + bce
    k_split_a3<<<cdiv(spHD, 256), 256>>>(out_xhat, A0, 4096, OUTD, KP_HD);
    k_split_bt3<<<dim3(KP_HD / 32, NP_HD / 32), tb>>>(Wlin2, B0, OUTD, OUTD, KP_HD, NP_HD);
    k_mma_gemm<<<gHD, 256, GEMM_SMEM>>>(A0, B0, p_t, OUTD, 3L * KP_HD, blin2, 1.0f, 0, 1);
    k_out_gemm<<<N_TRAIN, 256>>>(p_t, Wce, bce, out_y);
}